// round 1
// baseline (speedup 1.0000x reference)
#include <cuda_runtime.h>
#include <math.h>

// SO3Conv: out[b,g,off_l + v*d + m] = norm_l * sum_{f,u} x[b,f,off_l+u*d+m] * psi[f,g,off_l+u*d+v]
// psi[f,g,i] = (1/8) * sum_t D[t,i] * w[f,g,t]
// Per l: GEMM  C[M x N] = A[M x K] * W_l[K x N],  M=1024d, N=K=64d,
//   A[(b,m),(f,u)] gathered from x; W_l packed contiguous with norm folded.

#define IRREP   455
#define XSTRIDE 29120  // 64*455

__device__ float g_W[4096 * IRREP];  // packed per-l W matrices (same total size as psi)

__constant__ int c_off[8] = {0, 1, 10, 35, 84, 165, 286, 455};

__device__ __forceinline__ unsigned long long ffma2(unsigned long long a,
                                                    unsigned long long b,
                                                    unsigned long long c) {
    unsigned long long d;
    asm("fma.rn.f32x2 %0, %1, %2, %3;" : "=l"(d) : "l"(a), "l"(b), "l"(c));
    return d;
}

__device__ __forceinline__ unsigned long long dup2(float x) {
    unsigned long long r;
    unsigned xi = __float_as_uint(x);
    asm("mov.b64 %0, {%1, %1};" : "=l"(r) : "r"(xi));
    return r;
}

// divmod by small odd d via 32-bit magic (magic = ceil(2^32/d); magic==0 means d==1)
__device__ __forceinline__ void divmod_d(unsigned r, unsigned d, unsigned magic,
                                         unsigned& q, unsigned& rem) {
    if (magic == 0u) { q = r; rem = 0u; }
    else {
        q = (unsigned)(((unsigned long long)r * magic) >> 32);
        rem = r - q * d;
    }
}

// ---------------------------------------------------------------------------
// Build W: psi GEMM (4096 fg  x  455 i, K=64) with scatter into packed layout.
// Block tile: 64 fg x 64 i. 256 threads, 4x4 per thread.
// ---------------------------------------------------------------------------
__global__ void build_w_kernel(const float* __restrict__ D, const float* __restrict__ w) {
    __shared__ float wsT[64][68];  // [t][fg_local], padded for 16B-aligned rows
    __shared__ float Ds[64][64];   // [t][i_local]

    int tid = threadIdx.x;
    int fg0 = blockIdx.y << 6;
    int i0  = blockIdx.x << 6;

#pragma unroll
    for (int it = 0; it < 16; ++it) {
        int e = tid + (it << 8);
        int fgl = e >> 6, t = e & 63;
        wsT[t][fgl] = w[((fg0 + fgl) << 6) + t];
    }
#pragma unroll
    for (int it = 0; it < 16; ++it) {
        int e = tid + (it << 8);
        int t = e >> 6, il = e & 63;
        int i = i0 + il;
        Ds[t][il] = (i < IRREP) ? D[t * IRREP + i] : 0.f;
    }
    __syncthreads();

    int tr = (tid >> 4) << 2;
    int tc = (tid & 15) << 2;
    float acc[4][4] = {};
#pragma unroll
    for (int t = 0; t < 64; ++t) {
        float4 a = *(const float4*)&wsT[t][tr];
        float4 b = *(const float4*)&Ds[t][tc];
        float av[4] = {a.x, a.y, a.z, a.w};
        float bv[4] = {b.x, b.y, b.z, b.w};
#pragma unroll
        for (int j = 0; j < 4; ++j)
#pragma unroll
            for (int jj = 0; jj < 4; ++jj) acc[j][jj] += av[j] * bv[jj];
    }

    // Scatter: psi[fg][i] -> g_W[woff_l + (f*d+u)*(64d) + (g*d+v)] * (1/(64*sqrt(d)))
#pragma unroll
    for (int j = 0; j < 4; ++j) {
        int fg = fg0 + tr + j;
        int f = fg >> 6, g = fg & 63;
#pragma unroll
        for (int jj = 0; jj < 4; ++jj) {
            int i = i0 + tc + jj;
            if (i >= IRREP) continue;
            int l = 0;
#pragma unroll
            for (int t = 1; t < 7; ++t)
                if (i >= c_off[t]) l = t;
            int d   = 2 * l + 1;
            int off = c_off[l];
            int rel = i - off;
            int u = rel / d, v = rel % d;
            int N = d << 6;
            int woff = off << 12;  // 4096 * off
            float scale = rsqrtf((float)d) * 0.015625f;  // 1/(64*sqrt(d))
            g_W[woff + (f * d + u) * N + (g * d + v)] = acc[j][jj] * scale;
        }
    }
}

// ---------------------------------------------------------------------------
// Main GEMM per l: 128x128x16 tiles, 256 threads, 8x8 per thread, f32x2 FMAs.
// ---------------------------------------------------------------------------
__device__ __forceinline__ void load_tile(const float* __restrict__ xb,
                                          const float* __restrict__ Wb, bool nval,
                                          int k0, int khi, unsigned d, unsigned magic,
                                          int N, float ar[8], float br[8]) {
#pragma unroll
    for (int i = 0; i < 8; ++i) {
        unsigned k = (unsigned)(k0 + khi + 2 * i);
        unsigned f, u;
        divmod_d(k, d, magic, f, u);
        ar[i] = xb[f * 455 + u * d];
        br[i] = nval ? Wb[k * N] : 0.f;
    }
}

__global__ __launch_bounds__(256, 2)
void so3_gemm(const float* __restrict__ x, float* __restrict__ out,
              int d, int off, int woff, unsigned magic) {
    const int N  = d << 6;
    const int K  = d << 6;
    const int KT = K >> 4;

    __shared__ float As[16][128];
    __shared__ float Bs[16][128];

    int tid = threadIdx.x;
    int rlo = tid & 127;
    int khi = tid >> 7;
    int n0 = blockIdx.x << 7;

    // A gather base for this thread's fixed row slot
    unsigned rowA = (blockIdx.y << 7) + rlo;
    unsigned b, m;
    divmod_d(rowA, (unsigned)d, magic, b, m);
    const float* xb = x + (size_t)b * XSTRIDE + off + m;

    int nn = n0 + rlo;
    bool nval = nn < N;
    const float* Wb = g_W + woff + (nval ? nn : 0);

    unsigned long long acc[8][4] = {};
    float ar[8], br[8];
    load_tile(xb, Wb, nval, 0, khi, (unsigned)d, magic, N, ar, br);

    int trow = (tid >> 4) << 3;
    int tcol = (tid & 15) << 3;

#pragma unroll 1
    for (int kt = 0; kt < KT; ++kt) {
#pragma unroll
        for (int i = 0; i < 8; ++i) {
            As[khi + 2 * i][rlo] = ar[i];
            Bs[khi + 2 * i][rlo] = br[i];
        }
        __syncthreads();

        if (kt + 1 < KT)
            load_tile(xb, Wb, nval, (kt + 1) << 4, khi, (unsigned)d, magic, N, ar, br);

#pragma unroll
        for (int k = 0; k < 16; ++k) {
            float4 a0 = *(const float4*)&As[k][trow];
            float4 a1 = *(const float4*)&As[k][trow + 4];
            ulonglong2 b0 = *(const ulonglong2*)&Bs[k][tcol];
            ulonglong2 b1 = *(const ulonglong2*)&Bs[k][tcol + 4];
            float av[8] = {a0.x, a0.y, a0.z, a0.w, a1.x, a1.y, a1.z, a1.w};
            unsigned long long bp[4] = {b0.x, b0.y, b1.x, b1.y};
#pragma unroll
            for (int r = 0; r < 8; ++r) {
                unsigned long long a2 = dup2(av[r]);
#pragma unroll
                for (int c = 0; c < 4; ++c) acc[r][c] = ffma2(a2, bp[c], acc[r][c]);
            }
        }
        __syncthreads();
    }

    // Epilogue: scatter C[(b,m),(g,v)] -> out[b, g, off + v*d + m]
    int rowbase = (blockIdx.y << 7) + trow;
#pragma unroll
    for (int r = 0; r < 8; ++r) {
        unsigned row = (unsigned)(rowbase + r);
        unsigned bb, mm;
        divmod_d(row, (unsigned)d, magic, bb, mm);
        float* ob = out + (size_t)bb * XSTRIDE + off + mm;
#pragma unroll
        for (int c = 0; c < 4; ++c) {
            int col = n0 + tcol + 2 * c;
            unsigned long long v = acc[r][c];
            float lo = __uint_as_float((unsigned)v);
            float hi = __uint_as_float((unsigned)(v >> 32));
            if (col < N) {
                unsigned g, vv;
                divmod_d((unsigned)col, (unsigned)d, magic, g, vv);
                ob[g * 455 + vv * d] = lo;
            }
            if (col + 1 < N) {
                unsigned g, vv;
                divmod_d((unsigned)(col + 1), (unsigned)d, magic, g, vv);
                ob[g * 455 + vv * d] = hi;
            }
        }
    }
}

extern "C" void kernel_launch(void* const* d_in, const int* in_sizes, int n_in,
                              void* d_out, int out_size) {
    const float* x = (const float*)d_in[0];
    const float* D = (const float*)d_in[1];
    const float* w = (const float*)d_in[2];
    float* out = (float*)d_out;

    dim3 bgrid(8, 64);  // 8 i-tiles x 64 fg-tiles
    build_w_kernel<<<bgrid, 256>>>(D, w);

    int off = 0;
    for (int l = 0; l < 7; ++l) {
        int d = 2 * l + 1;
        int M = d << 10;  // 1024*d
        int N = d << 6;   // 64*d
        unsigned magic = (d == 1)
            ? 0u
            : (unsigned)((0x100000000ULL + (unsigned long long)d - 1) / (unsigned long long)d);
        dim3 grid((unsigned)((N + 127) >> 7), (unsigned)(M >> 7));
        so3_gemm<<<grid, 256>>>(x, out, d, off, off << 12, magic);
        off += d * d;
    }
}

// round 6
// speedup vs baseline: 2.4051x; 2.4051x over previous
#include <cuda_runtime.h>
#include <cuda_bf16.h>
#include <stdint.h>

#define IRREP 455
#define XSTR  29120   // 64*455

// Pre-split weights, per-l layout [n=(g*d+v)][k=(f*d+u)] K-major, norm folded.
__device__ __nv_bfloat16 g_Wh[4096 * IRREP];
__device__ __nv_bfloat16 g_Wl[4096 * IRREP];

__constant__ int      c_off[8]   = {0, 1, 10, 35, 84, 165, 286, 455};
__constant__ unsigned c_magic[7] = {0u, 1431655766u, 858993460u, 613566757u,
                                    477218589u, 390451573u, 330382100u};
__constant__ int      c_tile[8]  = {0, 8, 56, 176, 400, 760, 1288, 2016};

static __device__ __forceinline__ uint32_t smem_u32(const void* p) {
    uint32_t a;
    asm("{ .reg .u64 t; cvta.to.shared.u64 t, %1; cvt.u32.u64 %0, t; }" : "=r"(a) : "l"(p));
    return a;
}
static __device__ __forceinline__ void divmod_d(unsigned r, unsigned d, unsigned magic,
                                                unsigned& q, unsigned& rem) {
    if (magic == 0u) { q = r; rem = 0u; }
    else {
        q = (unsigned)(((unsigned long long)r * magic) >> 32);
        rem = r - q * d;
    }
}
static __device__ __forceinline__ unsigned cvt_bf16x2(float hi, float lo) {
    unsigned p;
    asm("cvt.rn.bf16x2.f32 %0, %1, %2;" : "=r"(p) : "f"(hi), "f"(lo));
    return p;
}
static __device__ __forceinline__ unsigned sw64(unsigned b) { return b ^ ((b >> 3) & 0x30u); }

static __device__ __forceinline__ void ldm4(uint32_t* r, uint32_t addr) {
    asm volatile("ldmatrix.sync.aligned.m8n8.x4.shared.b16 {%0,%1,%2,%3}, [%4];"
                 : "=r"(r[0]), "=r"(r[1]), "=r"(r[2]), "=r"(r[3]) : "r"(addr));
}
static __device__ __forceinline__ void mma_bf16(float* c, const uint32_t* a,
                                                uint32_t b0, uint32_t b1) {
    asm volatile(
        "mma.sync.aligned.m16n8k16.row.col.f32.bf16.bf16.f32 "
        "{%0,%1,%2,%3}, {%4,%5,%6,%7}, {%8,%9}, {%0,%1,%2,%3};"
        : "+f"(c[0]), "+f"(c[1]), "+f"(c[2]), "+f"(c[3])
        : "r"(a[0]), "r"(a[1]), "r"(a[2]), "r"(a[3]), "r"(b0), "r"(b1));
}
static __device__ __forceinline__ void cp16(uint32_t dst, const void* src, int szbytes) {
    asm volatile("cp.async.cg.shared.global [%0], [%1], 16, %2;"
                 :: "r"(dst), "l"(src), "r"(szbytes) : "memory");
}
static __device__ __forceinline__ void sts128(uint32_t addr, unsigned a, unsigned b,
                                              unsigned c, unsigned d) {
    asm volatile("st.shared.v4.b32 [%0], {%1,%2,%3,%4};"
                 :: "r"(addr), "r"(a), "r"(b), "r"(c), "r"(d) : "memory");
}

// ---------------------------------------------------------------------------
// build_w: psi = D^T w / 8, scatter -> bf16 hi/lo in [n][k] per-l layout,
// norm 1/(64 sqrt(d)) folded in.
// ---------------------------------------------------------------------------
__global__ void build_w_kernel(const float* __restrict__ D, const float* __restrict__ w) {
    __shared__ float wsT[64][68];
    __shared__ float Ds[64][64];

    int tid = threadIdx.x;
    int fg0 = blockIdx.y << 6;
    int i0  = blockIdx.x << 6;

#pragma unroll
    for (int it = 0; it < 16; ++it) {
        int e = tid + (it << 8);
        int fgl = e >> 6, t = e & 63;
        wsT[t][fgl] = w[((fg0 + fgl) << 6) + t];
    }
#pragma unroll
    for (int it = 0; it < 16; ++it) {
        int e = tid + (it << 8);
        int t = e >> 6, il = e & 63;
        int i = i0 + il;
        Ds[t][il] = (i < IRREP) ? D[t * IRREP + i] : 0.f;
    }
    __syncthreads();

    int tr = (tid >> 4) << 2;
    int tc = (tid & 15) << 2;
    float acc[4][4] = {};
#pragma unroll
    for (int t = 0; t < 64; ++t) {
        float4 a = *(const float4*)&wsT[t][tr];
        float4 b = *(const float4*)&Ds[t][tc];
        float av[4] = {a.x, a.y, a.z, a.w};
        float bv[4] = {b.x, b.y, b.z, b.w};
#pragma unroll
        for (int j = 0; j < 4; ++j)
#pragma unroll
            for (int jj = 0; jj < 4; ++jj) acc[j][jj] += av[j] * bv[jj];
    }

#pragma unroll
    for (int j = 0; j < 4; ++j) {
        int fg = fg0 + tr + j;
        int f = fg >> 6, g = fg & 63;
#pragma unroll
        for (int jj = 0; jj < 4; ++jj) {
            int i = i0 + tc + jj;
            if (i >= IRREP) continue;
            int l = 0;
#pragma unroll
            for (int t = 1; t < 7; ++t)
                if (i >= c_off[t]) l = t;
            int d   = 2 * l + 1;
            int off = c_off[l];
            int rel = i - off;
            int u = rel / d, v = rel % d;
            int K = d << 6;
            float val = acc[j][jj] * rsqrtf((float)d) * 0.015625f;
            __nv_bfloat16 h = __float2bfloat16(val);
            float resid = val - __bfloat162float(h);
            size_t idx = ((size_t)off << 12) + (size_t)(g * d + v) * K + (f * d + u);
            g_Wh[idx] = h;
            g_Wl[idx] = __float2bfloat16(resid);
        }
    }
}

// ---------------------------------------------------------------------------
// Fused mma.sync kernel: CTA = 128x128 C tile. BK=32 bf16, double-buffered.
// Stage layout (32KB): [Ah 8K][Al 8K][Bh 8K][Bl 8K], x2 stages = 64KB.
// 8 warps in 2x4: warp = 64m x 32n. 3-term bf16 split per k-step.
// ---------------------------------------------------------------------------
__global__ __launch_bounds__(256)
void so3_mma(const float* __restrict__ x, float* __restrict__ out) {
    extern __shared__ __align__(128) char dsm[];
    const uint32_t S0 = smem_u32(dsm);

    const int tid  = threadIdx.x;
    const int wid  = tid >> 5;
    const int lane = tid & 31;

    // ---- decode (l, rowTile, colTile) ----
    int bid = blockIdx.x, l = 0;
#pragma unroll
    for (int t = 1; t < 7; ++t)
        if (bid >= c_tile[t]) l = t;
    const int d        = 2 * l + 1;
    const int rem      = bid - c_tile[l];
    const int colTiles = (d + 1) >> 1;
    const int rowTile  = rem / colTiles;
    const int colTile  = rem - rowTile * colTiles;
    const int off      = c_off[l];
    const unsigned magic = c_magic[l];
    const int K  = d << 6;
    const int N  = d << 6;
    const int KT = 2 * d;            // K / 32
    const int n0 = colTile << 7;
    const int woff = off << 12;

    // ---- A fill setup: thread handles row r, k-range [kb, kb+16) per stage ----
    const int r  = tid & 127;
    const int kb = (tid >> 7) << 4;
    unsigned bq, mq;
    divmod_d((unsigned)(rowTile * 128 + r), (unsigned)d, magic, bq, mq);
    const float* xrow = x + (size_t)bq * XSTR + off + mq;
    const uint32_t sA0 = sw64((unsigned)(r * 64 + kb * 2));
    const uint32_t sA1 = sw64((unsigned)(r * 64 + kb * 2 + 16));

    // ---- B fill setup: 2 elems/thread (uint4 units), cp.async ----
    const int e0 = tid, e1 = tid + 256;
    const int rb0 = e0 >> 2, ch0 = e0 & 3;
    const int rb1 = e1 >> 2, ch1 = e1 & 3;
    const int sz0 = (n0 + rb0 < N) ? 16 : 0;
    const int sz1 = (n0 + rb1 < N) ? 16 : 0;
    const int rb0c = (n0 + rb0 < N) ? (n0 + rb0) : 0;
    const int rb1c = (n0 + rb1 < N) ? (n0 + rb1) : 0;
    const __nv_bfloat16* wh0 = g_Wh + woff + (size_t)rb0c * K + ch0 * 8;
    const __nv_bfloat16* wh1 = g_Wh + woff + (size_t)rb1c * K + ch1 * 8;
    const __nv_bfloat16* wl0 = g_Wl + woff + (size_t)rb0c * K + ch0 * 8;
    const __nv_bfloat16* wl1 = g_Wl + woff + (size_t)rb1c * K + ch1 * 8;
    const uint32_t dOff0 = sw64((unsigned)(rb0 * 64 + ch0 * 16));
    const uint32_t dOff1 = sw64((unsigned)(rb1 * 64 + ch1 * 16));

    // ---- compute setup ----
    const int m0  = (wid >> 2) << 6;   // 0 or 64
    const int n0w = (wid & 3) << 5;    // 0,32,64,96
    const int mat = lane >> 3;
    const int rowoffA = (lane & 7) + ((mat & 1) << 3);
    const int koffA   = (mat >> 1) << 3;
    const int rowoffB = (lane & 7) + ((mat >> 1) << 3);
    const int koffB   = (mat & 1) << 3;
    const uint32_t abase = (uint32_t)((m0 + rowoffA) * 64 + koffA * 2);
    const uint32_t bbase = (uint32_t)((n0w + rowoffB) * 64 + koffB * 2);

    float acc[4][4][4] = {};
    float areg[16];

    // ---- prologue: stage 0 ----
    {
        unsigned f, u;
        divmod_d((unsigned)kb, (unsigned)d, magic, f, u);
        const float* p = xrow + f * 455 + (int)u * d;
#pragma unroll
        for (int j = 0; j < 16; ++j) {
            areg[j] = *p; p += d;
            if (++u == (unsigned)d) { u = 0; p += 455 - d * d; }
        }
        cp16(S0 + 16384 + dOff0, wh0, sz0);
        cp16(S0 + 16384 + dOff1, wh1, sz1);
        cp16(S0 + 24576 + dOff0, wl0, sz0);
        cp16(S0 + 24576 + dOff1, wl1, sz1);
        // split + store A
        unsigned h[8], lo[8];
#pragma unroll
        for (int j = 0; j < 8; ++j) {
            unsigned pk = cvt_bf16x2(areg[2 * j + 1], areg[2 * j]);
            float h0 = __uint_as_float(pk << 16);
            float h1 = __uint_as_float(pk & 0xFFFF0000u);
            h[j]  = pk;
            lo[j] = cvt_bf16x2(areg[2 * j + 1] - h1, areg[2 * j] - h0);
        }
        sts128(S0 + sA0, h[0], h[1], h[2], h[3]);
        sts128(S0 + sA1, h[4], h[5], h[6], h[7]);
        sts128(S0 + 8192 + sA0, lo[0], lo[1], lo[2], lo[3]);
        sts128(S0 + 8192 + sA1, lo[4], lo[5], lo[6], lo[7]);
        asm volatile("cp.async.commit_group;");
        asm volatile("cp.async.wait_group 0;");
    }
    __syncthreads();

#pragma unroll 1
    for (int kt = 0; kt < KT; ++kt) {
        const uint32_t cb = S0 + (uint32_t)((kt & 1) * 32768);
        const uint32_t nb = S0 + (uint32_t)(((kt + 1) & 1) * 32768);
        const bool more = (kt + 1) < KT;

        if (more) {
            int k0 = (kt + 1) * 32 + kb;
            unsigned f, u;
            divmod_d((unsigned)k0, (unsigned)d, magic, f, u);
            const float* p = xrow + f * 455 + (int)u * d;
#pragma unroll
            for (int j = 0; j < 16; ++j) {
                areg[j] = *p; p += d;
                if (++u == (unsigned)d) { u = 0; p += 455 - d * d; }
            }
            const int ko = (kt + 1) * 32;
            cp16(nb + 16384 + dOff0, wh0 + ko, sz0);
            cp16(nb + 16384 + dOff1, wh1 + ko, sz1);
            cp16(nb + 24576 + dOff0, wl0 + ko, sz0);
            cp16(nb + 24576 + dOff1, wl1 + ko, sz1);
            asm volatile("cp.async.commit_group;");
        }

        // ---- compute on cb ----
#pragma unroll
        for (int ks = 0; ks < 2; ++ks) {
            uint32_t ah[4][4], al[4][4], bh[2][4], bl[2][4];
#pragma unroll
            for (int mi = 0; mi < 4; ++mi) {
                uint32_t ba = abase + (uint32_t)(mi * 1024 + ks * 32);
                ldm4(ah[mi], cb + sw64(ba));
                ldm4(al[mi], cb + 8192 + sw64(ba));
            }
#pragma unroll
            for (int bi = 0; bi < 2; ++bi) {
                uint32_t bb = bbase + (uint32_t)(bi * 1024 + ks * 32);
                ldm4(bh[bi], cb + 16384 + sw64(bb));
                ldm4(bl[bi], cb + 24576 + sw64(bb));
            }
#pragma unroll
            for (int mi = 0; mi < 4; ++mi)
#pragma unroll
                for (int ni = 0; ni < 4; ++ni) {
                    const uint32_t* bph = &bh[ni >> 1][(ni & 1) * 2];
                    const uint32_t* bpl = &bl[ni >> 1][(ni & 1) * 2];
                    mma_bf16(acc[mi][ni], ah[mi], bph[0], bph[1]);
                    mma_bf16(acc[mi][ni], al[mi], bph[0], bph[1]);
                    mma_bf16(acc[mi][ni], ah[mi], bpl[0], bpl[1]);
                }
        }

        if (more) {
            unsigned h[8], lo[8];
#pragma unroll
            for (int j = 0; j < 8; ++j) {
                unsigned pk = cvt_bf16x2(areg[2 * j + 1], areg[2 * j]);
                float h0 = __uint_as_float(pk << 16);
                float h1 = __uint_as_float(pk & 0xFFFF0000u);
                h[j]  = pk;
                lo[j] = cvt_bf16x2(areg[2 * j + 1] - h1, areg[2 * j] - h0);
            }
            sts128(nb + sA0, h[0], h[1], h[2], h[3]);
            sts128(nb + sA1, h[4], h[5], h[6], h[7]);
            sts128(nb + 8192 + sA0, lo[0], lo[1], lo[2], lo[3]);
            sts128(nb + 8192 + sA1, lo[4], lo[5], lo[6], lo[7]);
            asm volatile("cp.async.wait_group 0;");
        }
        __syncthreads();
    }

    // ---- epilogue: scattered stores ----
    float* rp[4][2];
#pragma unroll
    for (int mi = 0; mi < 4; ++mi)
#pragma unroll
        for (int rr = 0; rr < 2; ++rr) {
            unsigned rowg = (unsigned)(rowTile * 128 + m0 + 16 * mi + (lane >> 2) + rr * 8);
            unsigned b2, m2;
            divmod_d(rowg, (unsigned)d, magic, b2, m2);
            rp[mi][rr] = out + (size_t)b2 * XSTR + off + m2;
        }
    int  co[4][2];
    bool cv[4][2];
#pragma unroll
    for (int ni = 0; ni < 4; ++ni)
#pragma unroll
        for (int cc = 0; cc < 2; ++cc) {
            int n = n0 + n0w + 8 * ni + (lane & 3) * 2 + cc;
            cv[ni][cc] = n < N;
            unsigned g, v;
            divmod_d((unsigned)(cv[ni][cc] ? n : 0), (unsigned)d, magic, g, v);
            co[ni][cc] = (int)(g * 455 + v * d);
        }
#pragma unroll
    for (int mi = 0; mi < 4; ++mi)
#pragma unroll
        for (int ni = 0; ni < 4; ++ni) {
            const float* c = acc[mi][ni];
            if (cv[ni][0]) rp[mi][0][co[ni][0]] = c[0];
            if (cv[ni][1]) rp[mi][0][co[ni][1]] = c[1];
            if (cv[ni][0]) rp[mi][1][co[ni][0]] = c[2];
            if (cv[ni][1]) rp[mi][1][co[ni][1]] = c[3];
        }
}

extern "C" void kernel_launch(void* const* d_in, const int* in_sizes, int n_in,
                              void* d_out, int out_size) {
    const float* x = (const float*)d_in[0];
    const float* D = (const float*)d_in[1];
    const float* w = (const float*)d_in[2];
    float* out = (float*)d_out;

    dim3 bgrid(8, 64);
    build_w_kernel<<<bgrid, 256>>>(D, w);

    cudaFuncSetAttribute(so3_mma, cudaFuncAttributeMaxDynamicSharedMemorySize, 65536);
    so3_mma<<<2016, 256, 65536>>>(x, out);
}